// round 1
// baseline (speedup 1.0000x reference)
#include <cuda_runtime.h>
#include <math.h>

#define DT 0.01f
#define TWO_PI 6.28318530717958647692f

#define MAXB 4096
#define MAXN 4096
#define CCH  32           // number of batch chunks for the parallel scan

// Static device scratch (no allocations allowed)
__device__ float  g_force[(size_t)MAXB * MAXN];   // 64 MB: force = x @ W^T + b
__device__ float2 g_carry[CCH * MAXN];            // per-(chunk, col) local final (s, v)
__device__ float2 g_z[CCH * MAXN];                // per-(chunk, col) incoming (s, v)

// ---------------------------------------------------------------------------
// GEMM (NT): C[m, n] = sum_k A[m, k] * W[n, k] + bias[n]
// BM=BN=128, BK=16, 256 threads, 8x8 per-thread tile, float4 smem access.
// ---------------------------------------------------------------------------
#define BM 128
#define BN 128
#define BK 16
#define SPAD 4   // row stride = 132 floats (multiple of 4 -> 16B-aligned LDS.128)

__global__ __launch_bounds__(256) void gemm_nt_kernel(
    const float* __restrict__ A,      // [M, K]
    const float* __restrict__ Wm,     // [N, K]
    const float* __restrict__ bias,   // [N]
    int M, int K, int N)
{
    __shared__ float As[BK][BM + SPAD];
    __shared__ float Bs[BK][BN + SPAD];

    const int tid = threadIdx.x;
    const int m0 = blockIdx.y * BM;
    const int n0 = blockIdx.x * BN;

    const int tx = tid & 15;          // 0..15 -> n micro-tile
    const int ty = tid >> 4;          // 0..15 -> m micro-tile

    const int lrow = tid >> 2;        // 0..63
    const int lcol = (tid & 3) * 4;   // 0,4,8,12

    float acc[8][8];
    #pragma unroll
    for (int i = 0; i < 8; ++i)
        #pragma unroll
        for (int j = 0; j < 8; ++j)
            acc[i][j] = 0.0f;

    for (int k0 = 0; k0 < K; k0 += BK) {
        // Load A and W tiles (transposed into smem: [k][m])
        #pragma unroll
        for (int p = 0; p < 2; ++p) {
            int row = lrow + p * 64;
            float4 va = *reinterpret_cast<const float4*>(
                &A[(size_t)(m0 + row) * K + k0 + lcol]);
            As[lcol + 0][row] = va.x;
            As[lcol + 1][row] = va.y;
            As[lcol + 2][row] = va.z;
            As[lcol + 3][row] = va.w;
            float4 vb = *reinterpret_cast<const float4*>(
                &Wm[(size_t)(n0 + row) * K + k0 + lcol]);
            Bs[lcol + 0][row] = vb.x;
            Bs[lcol + 1][row] = vb.y;
            Bs[lcol + 2][row] = vb.z;
            Bs[lcol + 3][row] = vb.w;
        }
        __syncthreads();

        #pragma unroll
        for (int kk = 0; kk < BK; ++kk) {
            float4 a0 = *reinterpret_cast<const float4*>(&As[kk][ty * 8]);
            float4 a1 = *reinterpret_cast<const float4*>(&As[kk][ty * 8 + 4]);
            float4 b0 = *reinterpret_cast<const float4*>(&Bs[kk][tx * 8]);
            float4 b1 = *reinterpret_cast<const float4*>(&Bs[kk][tx * 8 + 4]);
            float ra[8] = {a0.x, a0.y, a0.z, a0.w, a1.x, a1.y, a1.z, a1.w};
            float rb[8] = {b0.x, b0.y, b0.z, b0.w, b1.x, b1.y, b1.z, b1.w};
            #pragma unroll
            for (int i = 0; i < 8; ++i)
                #pragma unroll
                for (int j = 0; j < 8; ++j)
                    acc[i][j] = fmaf(ra[i], rb[j], acc[i][j]);
        }
        __syncthreads();
    }

    // Epilogue: add bias, write force to scratch
    #pragma unroll
    for (int j = 0; j < 8; ++j) {
        float bj = bias[n0 + tx * 8 + j];
        #pragma unroll
        for (int i = 0; i < 8; ++i)
            acc[i][j] += bj;
    }
    #pragma unroll
    for (int i = 0; i < 8; ++i) {
        size_t row = (size_t)(m0 + ty * 8 + i);
        float* cp = &g_force[row * N + n0 + tx * 8];
        float4 o0 = make_float4(acc[i][0], acc[i][1], acc[i][2], acc[i][3]);
        float4 o1 = make_float4(acc[i][4], acc[i][5], acc[i][6], acc[i][7]);
        *reinterpret_cast<float4*>(cp) = o0;
        *reinterpret_cast<float4*>(cp + 4) = o1;
    }
}

// ---------------------------------------------------------------------------
// Phase 1: per-(column, chunk) local scan with zero initial state.
// Writes local states to out, final (s, v) to g_carry.
// ---------------------------------------------------------------------------
__global__ __launch_bounds__(256) void scan_local_kernel(
    const float* __restrict__ freq, const float* __restrict__ damp,
    float* __restrict__ out, int N, int L)
{
    int n = blockIdx.x * blockDim.x + threadIdx.x;
    int j = blockIdx.y;
    if (n >= N) return;

    float f = freq[n];
    float w2 = (TWO_PI * f) * (TWO_PI * f);
    float dmp = damp[n];

    float s = 0.0f, v = 0.0f;
    const float* fp = g_force + (size_t)j * L * N + n;
    float* op = out + (size_t)j * L * N + n;

    for (int k = 0; k < L; ++k) {
        float fr = fp[(size_t)k * N];
        float accel = fmaf(-w2, s, fmaf(-dmp, v, fr));
        v = fmaf(accel, DT, v);
        s = fmaf(v, DT, s);
        op[(size_t)k * N] = s;
    }
    g_carry[j * N + n] = make_float2(s, v);
}

// ---------------------------------------------------------------------------
// Phase 2: sequential carry combine across chunks.
// z_0 = 0; z_{j+1} = M^L z_j + carry_j. M^L via binary exponentiation.
// ---------------------------------------------------------------------------
__global__ __launch_bounds__(256) void combine_kernel(
    const float* __restrict__ freq, const float* __restrict__ damp,
    int N, int C, int L)
{
    int n = blockIdx.x * blockDim.x + threadIdx.x;
    if (n >= N) return;

    float f = freq[n];
    float w2 = (TWO_PI * f) * (TWO_PI * f);
    float dmp = damp[n];

    // One-step transition matrix M
    float b00 = 1.0f - w2 * DT * DT;
    float b01 = DT * (1.0f - dmp * DT);
    float b10 = -w2 * DT;
    float b11 = 1.0f - dmp * DT;

    // E = M^L (powers of M commute, so product order is irrelevant)
    float e00 = 1.0f, e01 = 0.0f, e10 = 0.0f, e11 = 1.0f;
    int p = L;
    while (p) {
        if (p & 1) {
            float t00 = b00 * e00 + b01 * e10;
            float t01 = b00 * e01 + b01 * e11;
            float t10 = b10 * e00 + b11 * e10;
            float t11 = b10 * e01 + b11 * e11;
            e00 = t00; e01 = t01; e10 = t10; e11 = t11;
        }
        float s00 = b00 * b00 + b01 * b10;
        float s01 = b00 * b01 + b01 * b11;
        float s10 = b10 * b00 + b11 * b10;
        float s11 = b10 * b01 + b11 * b11;
        b00 = s00; b01 = s01; b10 = s10; b11 = s11;
        p >>= 1;
    }

    float sz = 0.0f, vz = 0.0f;
    for (int j = 0; j < C; ++j) {
        g_z[j * N + n] = make_float2(sz, vz);
        float2 c = g_carry[j * N + n];
        float ns = e00 * sz + e01 * vz + c.x;
        float nv = e10 * sz + e11 * vz + c.y;
        sz = ns; vz = nv;
    }
}

// ---------------------------------------------------------------------------
// Phase 3: fix-up. out[r] = clip(local[r] + (M^{k+1} z_chunk).s + osc, +-1)
// Homogeneous propagation uses the identical step form -> exact M powers.
// ---------------------------------------------------------------------------
__global__ __launch_bounds__(256) void fixup_kernel(
    const float* __restrict__ freq, const float* __restrict__ damp,
    const float* __restrict__ amp, const float* __restrict__ phase,
    float* __restrict__ out, int N, int L)
{
    int n = blockIdx.x * blockDim.x + threadIdx.x;
    int j = blockIdx.y;
    if (n >= N) return;

    float f = freq[n];
    float w2 = (TWO_PI * f) * (TWO_PI * f);
    float dmp = damp[n];
    float osc = amp[n] * sinf(fmaf(TWO_PI * f, DT, phase[n]));

    float2 zz = g_z[j * N + n];
    float s = zz.x, v = zz.y;

    float* op = out + (size_t)j * L * N + n;
    for (int k = 0; k < L; ++k) {
        float accel = fmaf(-w2, s, -dmp * v);
        v = fmaf(accel, DT, v);
        s = fmaf(v, DT, s);
        float o = op[(size_t)k * N] + s + osc;
        o = fminf(1.0f, fmaxf(-1.0f, o));
        op[(size_t)k * N] = o;
    }
}

// ---------------------------------------------------------------------------
extern "C" void kernel_launch(void* const* d_in, const int* in_sizes, int n_in,
                              void* d_out, int out_size)
{
    const float* x     = (const float*)d_in[0];
    const float* W     = (const float*)d_in[1];
    const float* b     = (const float*)d_in[2];
    const float* amp   = (const float*)d_in[3];
    const float* freq  = (const float*)d_in[4];
    const float* phase = (const float*)d_in[5];
    const float* damp  = (const float*)d_in[6];
    float* out = (float*)d_out;

    const int N = in_sizes[2];            // 4096
    const int D = in_sizes[1] / N;        // 2048
    const int B = in_sizes[0] / D;        // 4096
    const int C = CCH;                    // 32 chunks
    const int L = B / C;                  // 128 rows per chunk
    (void)n_in; (void)out_size;

    // 1. force = x @ W^T + b  -> g_force
    dim3 ggrid(N / BN, B / BM);
    gemm_nt_kernel<<<ggrid, 256>>>(x, W, b, B, D, N);

    // 2. per-chunk local scan (zero init) -> out (local states), g_carry
    dim3 sgrid((N + 255) / 256, C);
    scan_local_kernel<<<sgrid, 256>>>(freq, damp, out, N, L);

    // 3. combine carries across chunks -> g_z
    combine_kernel<<<(N + 255) / 256, 256>>>(freq, damp, N, C, L);

    // 4. fix-up: add homogeneous correction + oscillator, clip
    fixup_kernel<<<sgrid, 256>>>(freq, damp, amp, phase, out, N, L);
}

// round 3
// speedup vs baseline: 2.1540x; 2.1540x over previous
#include <cuda_runtime.h>
#include <cuda_bf16.h>
#include <math.h>
#include <stdint.h>

#define DT 0.01f
#define TWO_PI 6.28318530717958647692f

#define BSZ 4096
#define DSZ 2048
#define NSZ 4096

// scan chunking
#define CCH 128
#define LCH (BSZ / CCH)   // 32

// GEMM tiling
#define GBM 128
#define GBN 128
#define GBK 32                    // bf16 elems per stage (two k16 micro-steps)
#define ROWB 80                   // padded smem row bytes (64B data + 16B pad)
#define TILEB (128 * ROWB)        // 10240 bytes per matrix tile
#define STAGEB (4 * TILEB)        // Ahi, Alo, Bhi, Blo
#define NSTG 3
#define KITERS (DSZ / GBK)        // 64
#define SMEM_BYTES (NSTG * STAGEB) // 122880

// ---------------- static device scratch (no allocations allowed) -----------
__device__ __nv_bfloat16 g_Ahi[(size_t)BSZ * DSZ];
__device__ __nv_bfloat16 g_Alo[(size_t)BSZ * DSZ];
__device__ __nv_bfloat16 g_Whi[(size_t)NSZ * DSZ];
__device__ __nv_bfloat16 g_Wlo[(size_t)NSZ * DSZ];
__device__ float g_force[(size_t)BSZ * NSZ];
__device__ float g_cs[CCH * NSZ], g_cv[CCH * NSZ];
__device__ float g_zs[CCH * NSZ], g_zv[CCH * NSZ];

// ---------------- helpers --------------------------------------------------
__device__ __forceinline__ uint32_t smem_u32(const void* p) {
    uint32_t a;
    asm("{ .reg .u64 t; cvta.to.shared.u64 t, %1; cvt.u32.u64 %0, t; }" : "=r"(a) : "l"(p));
    return a;
}
__device__ __forceinline__ void cp16(uint32_t dst, const void* src) {
    asm volatile("cp.async.cg.shared.global [%0], [%1], 16;\n" :: "r"(dst), "l"(src));
}
__device__ __forceinline__ void ldsm_x4(uint32_t* r, uint32_t addr) {
    asm volatile("ldmatrix.sync.aligned.m8n8.x4.shared.b16 {%0,%1,%2,%3}, [%4];"
                 : "=r"(r[0]), "=r"(r[1]), "=r"(r[2]), "=r"(r[3]) : "r"(addr));
}
__device__ __forceinline__ void ldsm_x2(uint32_t* r, uint32_t addr) {
    asm volatile("ldmatrix.sync.aligned.m8n8.x2.shared.b16 {%0,%1}, [%2];"
                 : "=r"(r[0]), "=r"(r[1]) : "r"(addr));
}
__device__ __forceinline__ void mma_bf16(float* d, const uint32_t* a, const uint32_t* b) {
    asm volatile(
        "mma.sync.aligned.m16n8k16.row.col.f32.bf16.bf16.f32 "
        "{%0,%1,%2,%3}, {%4,%5,%6,%7}, {%8,%9}, {%0,%1,%2,%3};"
        : "+f"(d[0]), "+f"(d[1]), "+f"(d[2]), "+f"(d[3])
        : "r"(a[0]), "r"(a[1]), "r"(a[2]), "r"(a[3]), "r"(b[0]), "r"(b[1]));
}

// ---------------- split kernels: fp32 -> bf16 hi + bf16 lo -----------------
__device__ __forceinline__ void split4(float4 a, uint2& hi, uint2& lo) {
    __nv_bfloat16 hx = __float2bfloat16_rn(a.x);
    __nv_bfloat16 hy = __float2bfloat16_rn(a.y);
    __nv_bfloat16 hz = __float2bfloat16_rn(a.z);
    __nv_bfloat16 hw = __float2bfloat16_rn(a.w);
    __nv_bfloat16 lx = __float2bfloat16_rn(a.x - __bfloat162float(hx));
    __nv_bfloat16 ly = __float2bfloat16_rn(a.y - __bfloat162float(hy));
    __nv_bfloat16 lz = __float2bfloat16_rn(a.z - __bfloat162float(hz));
    __nv_bfloat16 lw = __float2bfloat16_rn(a.w - __bfloat162float(hw));
    hi.x = ((uint32_t)__bfloat16_as_ushort(hy) << 16) | __bfloat16_as_ushort(hx);
    hi.y = ((uint32_t)__bfloat16_as_ushort(hw) << 16) | __bfloat16_as_ushort(hz);
    lo.x = ((uint32_t)__bfloat16_as_ushort(ly) << 16) | __bfloat16_as_ushort(lx);
    lo.y = ((uint32_t)__bfloat16_as_ushort(lw) << 16) | __bfloat16_as_ushort(lz);
}
__global__ __launch_bounds__(256) void splitA_kernel(const float* __restrict__ src) {
    size_t i = (size_t)blockIdx.x * 256 + threadIdx.x;
    float4 a = reinterpret_cast<const float4*>(src)[i];
    uint2 h, l;
    split4(a, h, l);
    reinterpret_cast<uint2*>(g_Ahi)[i] = h;
    reinterpret_cast<uint2*>(g_Alo)[i] = l;
}
__global__ __launch_bounds__(256) void splitW_kernel(const float* __restrict__ src) {
    size_t i = (size_t)blockIdx.x * 256 + threadIdx.x;
    float4 a = reinterpret_cast<const float4*>(src)[i];
    uint2 h, l;
    split4(a, h, l);
    reinterpret_cast<uint2*>(g_Whi)[i] = h;
    reinterpret_cast<uint2*>(g_Wlo)[i] = l;
}

// ---------------- bf16x3 mma.sync GEMM: force = x @ W^T + b ---------------
__global__ __launch_bounds__(256, 1) void gemm_bf16x3_kernel(const float* __restrict__ bias) {
    extern __shared__ char smem_raw[];
    const uint32_t sbase = smem_u32(smem_raw);
    const int tid = threadIdx.x;
    const int lane = tid & 31;
    const int wid = tid >> 5;
    const int m0 = blockIdx.y * GBM;
    const int n0 = blockIdx.x * GBN;
    const int wm = (wid >> 2) * 64;   // 2 warp rows
    const int wn = (wid & 3) * 32;    // 4 warp cols

    float acc[4][4][4];
    #pragma unroll
    for (int mt = 0; mt < 4; ++mt)
        #pragma unroll
        for (int nt = 0; nt < 4; ++nt)
            #pragma unroll
            for (int r = 0; r < 4; ++r)
                acc[mt][nt][r] = 0.0f;

    // ---- stage loader: 512 16B chunks per matrix, 2 per thread ----
    auto load_stage = [&](int s, int buf) {
        uint32_t sb = sbase + (uint32_t)buf * STAGEB;
        int k0 = s * GBK;
        #pragma unroll
        for (int it = 0; it < 2; ++it) {
            int c = tid + it * 256;
            int row = c >> 2, c16 = c & 3;
            uint32_t soff = (uint32_t)row * ROWB + (uint32_t)c16 * 16;
            size_t gA = (size_t)(m0 + row) * DSZ + k0 + c16 * 8;
            size_t gB = (size_t)(n0 + row) * DSZ + k0 + c16 * 8;
            cp16(sb + soff, g_Ahi + gA);
            cp16(sb + TILEB + soff, g_Alo + gA);
            cp16(sb + 2 * TILEB + soff, g_Whi + gB);
            cp16(sb + 3 * TILEB + soff, g_Wlo + gB);
        }
    };

    load_stage(0, 0);
    asm volatile("cp.async.commit_group;\n" ::: "memory");
    load_stage(1, 1);
    asm volatile("cp.async.commit_group;\n" ::: "memory");

    for (int s = 0; s < KITERS; ++s) {
        if (s + 1 < KITERS)
            asm volatile("cp.async.wait_group 1;\n" ::: "memory");
        else
            asm volatile("cp.async.wait_group 0;\n" ::: "memory");
        __syncthreads();

        const uint32_t sb = sbase + (uint32_t)(s % NSTG) * STAGEB;
        #pragma unroll
        for (int ks = 0; ks < 2; ++ks) {
            uint32_t ahi[4][4], alo[4][4], bhi[4][2], blo[4][2];
            const uint32_t acol = (uint32_t)(ks * 32 + ((lane >> 4) & 1) * 16);
            const uint32_t bcol = (uint32_t)(ks * 32 + ((lane >> 3) & 1) * 16);
            #pragma unroll
            for (int mt = 0; mt < 4; ++mt) {
                uint32_t addr = sb + (uint32_t)(wm + mt * 16 + (lane & 15)) * ROWB + acol;
                ldsm_x4(ahi[mt], addr);
                ldsm_x4(alo[mt], addr + TILEB);
            }
            #pragma unroll
            for (int nt = 0; nt < 4; ++nt) {
                uint32_t addr = sb + 2 * TILEB +
                                (uint32_t)(wn + nt * 8 + (lane & 7)) * ROWB + bcol;
                ldsm_x2(bhi[nt], addr);
                ldsm_x2(blo[nt], addr + TILEB);
            }
            #pragma unroll
            for (int mt = 0; mt < 4; ++mt)
                #pragma unroll
                for (int nt = 0; nt < 4; ++nt) {
                    mma_bf16(acc[mt][nt], ahi[mt], bhi[nt]);
                    mma_bf16(acc[mt][nt], ahi[mt], blo[nt]);
                    mma_bf16(acc[mt][nt], alo[mt], bhi[nt]);
                }
        }
        __syncthreads();
        if (s + 2 < KITERS) {
            load_stage(s + 2, (s + 2) % NSTG);
            asm volatile("cp.async.commit_group;\n" ::: "memory");
        }
    }

    // ---- epilogue: add bias, write force ----
    #pragma unroll
    for (int nt = 0; nt < 4; ++nt) {
        int c = n0 + wn + nt * 8 + (lane & 3) * 2;
        float b0 = __ldg(&bias[c]);
        float b1 = __ldg(&bias[c + 1]);
        #pragma unroll
        for (int mt = 0; mt < 4; ++mt) {
            int r = m0 + wm + mt * 16 + (lane >> 2);
            float2 lo = make_float2(acc[mt][nt][0] + b0, acc[mt][nt][1] + b1);
            float2 hi = make_float2(acc[mt][nt][2] + b0, acc[mt][nt][3] + b1);
            *reinterpret_cast<float2*>(&g_force[(size_t)r * NSZ + c]) = lo;
            *reinterpret_cast<float2*>(&g_force[(size_t)(r + 8) * NSZ + c]) = hi;
        }
    }
}

// ---------------- scan phase A: per-chunk carries (zero init) -------------
__global__ __launch_bounds__(256) void scanA_kernel(const float* __restrict__ freq,
                                                    const float* __restrict__ damp) {
    int c4 = blockIdx.x * 256 + threadIdx.x;
    int j = blockIdx.y;
    int n = c4 * 4;
    float4 f4 = *reinterpret_cast<const float4*>(freq + n);
    float4 d4 = *reinterpret_cast<const float4*>(damp + n);
    float wx = (TWO_PI * f4.x) * (TWO_PI * f4.x);
    float wy = (TWO_PI * f4.y) * (TWO_PI * f4.y);
    float wz = (TWO_PI * f4.z) * (TWO_PI * f4.z);
    float ww = (TWO_PI * f4.w) * (TWO_PI * f4.w);
    float sx = 0, sy = 0, sz = 0, sw = 0, vx = 0, vy = 0, vz = 0, vw = 0;
    const float4* fp = reinterpret_cast<const float4*>(g_force + (size_t)j * LCH * NSZ + n);
    #pragma unroll 8
    for (int k = 0; k < LCH; ++k) {
        float4 fr = fp[(size_t)k * (NSZ / 4)];
        float ax = fmaf(-wx, sx, fmaf(-d4.x, vx, fr.x)); vx = fmaf(ax, DT, vx); sx = fmaf(vx, DT, sx);
        float ay = fmaf(-wy, sy, fmaf(-d4.y, vy, fr.y)); vy = fmaf(ay, DT, vy); sy = fmaf(vy, DT, sy);
        float az = fmaf(-wz, sz, fmaf(-d4.z, vz, fr.z)); vz = fmaf(az, DT, vz); sz = fmaf(vz, DT, sz);
        float aw = fmaf(-ww, sw, fmaf(-d4.w, vw, fr.w)); vw = fmaf(aw, DT, vw); sw = fmaf(vw, DT, sw);
    }
    *reinterpret_cast<float4*>(g_cs + (size_t)j * NSZ + n) = make_float4(sx, sy, sz, sw);
    *reinterpret_cast<float4*>(g_cv + (size_t)j * NSZ + n) = make_float4(vx, vy, vz, vw);
}

// ---------------- combine: z_{j+1} = M^L z_j + carry_j --------------------
__global__ __launch_bounds__(256) void combine_kernel(const float* __restrict__ freq,
                                                      const float* __restrict__ damp) {
    int n = blockIdx.x * 256 + threadIdx.x;
    float f = freq[n], dmp = damp[n];
    float w2 = (TWO_PI * f) * (TWO_PI * f);
    float b00 = 1.0f - w2 * DT * DT;
    float b01 = DT * (1.0f - dmp * DT);
    float b10 = -w2 * DT;
    float b11 = 1.0f - dmp * DT;
    float e00 = 1.0f, e01 = 0.0f, e10 = 0.0f, e11 = 1.0f;
    int p = LCH;
    while (p) {
        if (p & 1) {
            float t00 = b00 * e00 + b01 * e10, t01 = b00 * e01 + b01 * e11;
            float t10 = b10 * e00 + b11 * e10, t11 = b10 * e01 + b11 * e11;
            e00 = t00; e01 = t01; e10 = t10; e11 = t11;
        }
        float s00 = b00 * b00 + b01 * b10, s01 = b00 * b01 + b01 * b11;
        float s10 = b10 * b00 + b11 * b10, s11 = b10 * b01 + b11 * b11;
        b00 = s00; b01 = s01; b10 = s10; b11 = s11;
        p >>= 1;
    }
    float sz = 0.0f, vz = 0.0f;
    for (int j = 0; j < CCH; ++j) {
        g_zs[j * NSZ + n] = sz;
        g_zv[j * NSZ + n] = vz;
        float cs = g_cs[j * NSZ + n], cv = g_cv[j * NSZ + n];
        float ns = e00 * sz + e01 * vz + cs;
        float nv = e10 * sz + e11 * vz + cv;
        sz = ns; vz = nv;
    }
}

// ---------------- scan phase B: full scan from z, + osc, clip, write ------
__global__ __launch_bounds__(256) void scanB_kernel(const float* __restrict__ freq,
                                                    const float* __restrict__ damp,
                                                    const float* __restrict__ amp,
                                                    const float* __restrict__ phase,
                                                    float* __restrict__ out) {
    int c4 = blockIdx.x * 256 + threadIdx.x;
    int j = blockIdx.y;
    int n = c4 * 4;
    float4 f4 = *reinterpret_cast<const float4*>(freq + n);
    float4 d4 = *reinterpret_cast<const float4*>(damp + n);
    float4 a4 = *reinterpret_cast<const float4*>(amp + n);
    float4 p4 = *reinterpret_cast<const float4*>(phase + n);
    float wx = (TWO_PI * f4.x) * (TWO_PI * f4.x);
    float wy = (TWO_PI * f4.y) * (TWO_PI * f4.y);
    float wz = (TWO_PI * f4.z) * (TWO_PI * f4.z);
    float ww = (TWO_PI * f4.w) * (TWO_PI * f4.w);
    float ox = a4.x * sinf(fmaf(TWO_PI * f4.x, DT, p4.x));
    float oy = a4.y * sinf(fmaf(TWO_PI * f4.y, DT, p4.y));
    float oz = a4.z * sinf(fmaf(TWO_PI * f4.z, DT, p4.z));
    float ow = a4.w * sinf(fmaf(TWO_PI * f4.w, DT, p4.w));
    float4 zs = *reinterpret_cast<const float4*>(g_zs + (size_t)j * NSZ + n);
    float4 zv = *reinterpret_cast<const float4*>(g_zv + (size_t)j * NSZ + n);
    float sx = zs.x, sy = zs.y, szz = zs.z, sww = zs.w;
    float vx = zv.x, vy = zv.y, vzz = zv.z, vww = zv.w;
    const float4* fp = reinterpret_cast<const float4*>(g_force + (size_t)j * LCH * NSZ + n);
    float4* op = reinterpret_cast<float4*>(out + (size_t)j * LCH * NSZ + n);
    #pragma unroll 8
    for (int k = 0; k < LCH; ++k) {
        float4 fr = fp[(size_t)k * (NSZ / 4)];
        float ax = fmaf(-wx, sx, fmaf(-d4.x, vx, fr.x)); vx = fmaf(ax, DT, vx); sx = fmaf(vx, DT, sx);
        float ay = fmaf(-wy, sy, fmaf(-d4.y, vy, fr.y)); vy = fmaf(ay, DT, vy); sy = fmaf(vy, DT, sy);
        float az = fmaf(-wz, szz, fmaf(-d4.z, vzz, fr.z)); vzz = fmaf(az, DT, vzz); szz = fmaf(vzz, DT, szz);
        float aw = fmaf(-ww, sww, fmaf(-d4.w, vww, fr.w)); vww = fmaf(aw, DT, vww); sww = fmaf(vww, DT, sww);
        float4 o;
        o.x = fminf(1.0f, fmaxf(-1.0f, sx + ox));
        o.y = fminf(1.0f, fmaxf(-1.0f, sy + oy));
        o.z = fminf(1.0f, fmaxf(-1.0f, szz + oz));
        o.w = fminf(1.0f, fmaxf(-1.0f, sww + ow));
        op[(size_t)k * (NSZ / 4)] = o;
    }
}

// ---------------------------------------------------------------------------
extern "C" void kernel_launch(void* const* d_in, const int* in_sizes, int n_in,
                              void* d_out, int out_size)
{
    const float* x     = (const float*)d_in[0];
    const float* W     = (const float*)d_in[1];
    const float* b     = (const float*)d_in[2];
    const float* amp   = (const float*)d_in[3];
    const float* freq  = (const float*)d_in[4];
    const float* phase = (const float*)d_in[5];
    const float* damp  = (const float*)d_in[6];
    float* out = (float*)d_out;
    (void)in_sizes; (void)n_in; (void)out_size;

    static bool attr_done = false;
    if (!attr_done) {
        cudaFuncSetAttribute(gemm_bf16x3_kernel,
                             cudaFuncAttributeMaxDynamicSharedMemorySize, SMEM_BYTES);
        attr_done = true;
    }

    // 1. split operands into bf16 hi + bf16 residual lo
    splitA_kernel<<<(BSZ * DSZ / 4) / 256, 256>>>(x);
    splitW_kernel<<<(NSZ * DSZ / 4) / 256, 256>>>(W);

    // 2. bf16x3 tensor-core GEMM -> g_force (bias fused in epilogue)
    dim3 ggrid(NSZ / GBN, BSZ / GBM);
    gemm_bf16x3_kernel<<<ggrid, 256, SMEM_BYTES>>>(b);

    // 3. chunked parallel scan
    dim3 sgrid(NSZ / 4 / 256, CCH);
    scanA_kernel<<<sgrid, 256>>>(freq, damp);
    combine_kernel<<<NSZ / 256, 256>>>(freq, damp);
    scanB_kernel<<<sgrid, 256>>>(freq, damp, amp, phase, out);
}

// round 6
// speedup vs baseline: 2.1593x; 1.0025x over previous
#include <cuda_runtime.h>
#include <cuda_bf16.h>
#include <math.h>
#include <stdint.h>

#define DT 0.01f
#define TWO_PI 6.28318530717958647692f

#define BSZ 4096
#define DSZ 2048
#define NSZ 4096

// scan chunking
#define CCH 128
#define LCH (BSZ / CCH)   // 32

// GEMM tiling
#define GBM 128
#define GBN 128
#define GBK 32                    // bf16 elems per stage (two k16 micro-steps)
#define ROWB 80                   // padded smem row bytes (64B data + 16B pad)
#define TILEB (128 * ROWB)        // 10240 bytes per matrix tile
#define STAGEB (4 * TILEB)        // Ahi, Alo, Bhi, Blo
#define NSTG 3
#define KITERS (DSZ / GBK)        // 64
#define SMEM_BYTES (NSTG * STAGEB) // 122880

// ---------------- static device scratch (no allocations allowed) -----------
__device__ __nv_bfloat16 g_Ahi[(size_t)BSZ * DSZ];
__device__ __nv_bfloat16 g_Alo[(size_t)BSZ * DSZ];
__device__ __nv_bfloat16 g_Whi[(size_t)NSZ * DSZ];
__device__ __nv_bfloat16 g_Wlo[(size_t)NSZ * DSZ];
__device__ float g_force[(size_t)BSZ * NSZ];
__device__ float g_cs[CCH * NSZ], g_cv[CCH * NSZ];
__device__ float g_zs[CCH * NSZ], g_zv[CCH * NSZ];

// ---------------- helpers --------------------------------------------------
__device__ __forceinline__ uint32_t smem_u32(const void* p) {
    uint32_t a;
    asm("{ .reg .u64 t; cvta.to.shared.u64 t, %1; cvt.u32.u64 %0, t; }" : "=r"(a) : "l"(p));
    return a;
}
__device__ __forceinline__ void cp16(uint32_t dst, const void* src) {
    asm volatile("cp.async.cg.shared.global [%0], [%1], 16;\n" :: "r"(dst), "l"(src));
}
__device__ __forceinline__ void ldsm_x4(uint32_t* r, uint32_t addr) {
    asm volatile("ldmatrix.sync.aligned.m8n8.x4.shared.b16 {%0,%1,%2,%3}, [%4];"
                 : "=r"(r[0]), "=r"(r[1]), "=r"(r[2]), "=r"(r[3]) : "r"(addr));
}
__device__ __forceinline__ void mma_bf16(float* d, const uint32_t* a, const uint32_t* b) {
    asm volatile(
        "mma.sync.aligned.m16n8k16.row.col.f32.bf16.bf16.f32 "
        "{%0,%1,%2,%3}, {%4,%5,%6,%7}, {%8,%9}, {%0,%1,%2,%3};"
        : "+f"(d[0]), "+f"(d[1]), "+f"(d[2]), "+f"(d[3])
        : "r"(a[0]), "r"(a[1]), "r"(a[2]), "r"(a[3]), "r"(b[0]), "r"(b[1]));
}

// ---------------- split kernels: fp32 -> bf16 hi + bf16 lo -----------------
__device__ __forceinline__ void split4(float4 a, uint2& hi, uint2& lo) {
    __nv_bfloat16 hx = __float2bfloat16_rn(a.x);
    __nv_bfloat16 hy = __float2bfloat16_rn(a.y);
    __nv_bfloat16 hz = __float2bfloat16_rn(a.z);
    __nv_bfloat16 hw = __float2bfloat16_rn(a.w);
    __nv_bfloat16 lx = __float2bfloat16_rn(a.x - __bfloat162float(hx));
    __nv_bfloat16 ly = __float2bfloat16_rn(a.y - __bfloat162float(hy));
    __nv_bfloat16 lz = __float2bfloat16_rn(a.z - __bfloat162float(hz));
    __nv_bfloat16 lw = __float2bfloat16_rn(a.w - __bfloat162float(hw));
    hi.x = ((uint32_t)__bfloat16_as_ushort(hy) << 16) | __bfloat16_as_ushort(hx);
    hi.y = ((uint32_t)__bfloat16_as_ushort(hw) << 16) | __bfloat16_as_ushort(hz);
    lo.x = ((uint32_t)__bfloat16_as_ushort(ly) << 16) | __bfloat16_as_ushort(lx);
    lo.y = ((uint32_t)__bfloat16_as_ushort(lw) << 16) | __bfloat16_as_ushort(lz);
}
__global__ __launch_bounds__(256) void splitA_kernel(const float* __restrict__ src) {
    size_t i = (size_t)blockIdx.x * 256 + threadIdx.x;
    float4 a = reinterpret_cast<const float4*>(src)[i];
    uint2 h, l;
    split4(a, h, l);
    reinterpret_cast<uint2*>(g_Ahi)[i] = h;
    reinterpret_cast<uint2*>(g_Alo)[i] = l;
}
__global__ __launch_bounds__(256) void splitW_kernel(const float* __restrict__ src) {
    size_t i = (size_t)blockIdx.x * 256 + threadIdx.x;
    float4 a = reinterpret_cast<const float4*>(src)[i];
    uint2 h, l;
    split4(a, h, l);
    reinterpret_cast<uint2*>(g_Whi)[i] = h;
    reinterpret_cast<uint2*>(g_Wlo)[i] = l;
}

// ---------------- bf16x3 mma.sync GEMM: force = x @ W^T + b ---------------
struct Frag {
    uint32_t ahi[4][4], alo[4][4];
    uint32_t bhi[2][4], blo[2][4];
};

__global__ __launch_bounds__(256, 1) void gemm_bf16x3_kernel(const float* __restrict__ bias) {
    extern __shared__ char smem_raw[];
    const uint32_t sbase = smem_u32(smem_raw);
    const int tid = threadIdx.x;
    const int lane = tid & 31;
    const int wid = tid >> 5;
    const int m0 = blockIdx.y * GBM;
    const int n0 = blockIdx.x * GBN;
    const int wm = (wid >> 2) * 64;   // 2 warp rows
    const int wn = (wid & 3) * 32;    // 4 warp cols

    float acc[4][4][4];
    #pragma unroll
    for (int mt = 0; mt < 4; ++mt)
        #pragma unroll
        for (int nt = 0; nt < 4; ++nt)
            #pragma unroll
            for (int r = 0; r < 4; ++r)
                acc[mt][nt][r] = 0.0f;

    // precomputed lane-dependent ldmatrix address pieces
    const uint32_t a_row_off = (uint32_t)(wm + (lane & 15)) * ROWB;
    const uint32_t a_csel = ((lane >> 4) & 1) * 16;
    const uint32_t b_row_off = (uint32_t)(wn + ((lane >> 4) & 1) * 8 + (lane & 7)) * ROWB;
    const uint32_t b_csel = ((lane >> 3) & 1) * 16;

    auto load_stage = [&](int s, int buf) {
        uint32_t sb = sbase + (uint32_t)buf * STAGEB;
        int k0 = s * GBK;
        #pragma unroll
        for (int it = 0; it < 2; ++it) {
            int c = tid + it * 256;
            int row = c >> 2, c16 = c & 3;
            uint32_t soff = (uint32_t)row * ROWB + (uint32_t)c16 * 16;
            size_t gA = (size_t)(m0 + row) * DSZ + k0 + c16 * 8;
            size_t gB = (size_t)(n0 + row) * DSZ + k0 + c16 * 8;
            cp16(sb + soff, g_Ahi + gA);
            cp16(sb + TILEB + soff, g_Alo + gA);
            cp16(sb + 2 * TILEB + soff, g_Whi + gB);
            cp16(sb + 3 * TILEB + soff, g_Wlo + gB);
        }
    };

    auto load_frags = [&](Frag& f, uint32_t sb, int ks) {
        const uint32_t acol = (uint32_t)(ks * 32) + a_csel;
        const uint32_t bcol = (uint32_t)(ks * 32) + b_csel;
        #pragma unroll
        for (int mt = 0; mt < 4; ++mt) {
            uint32_t addr = sb + a_row_off + (uint32_t)(mt * 16) * ROWB + acol;
            ldsm_x4(f.ahi[mt], addr);
            ldsm_x4(f.alo[mt], addr + TILEB);
        }
        #pragma unroll
        for (int ntp = 0; ntp < 2; ++ntp) {
            uint32_t addr = sb + 2 * TILEB + b_row_off + (uint32_t)(ntp * 16) * ROWB + bcol;
            ldsm_x4(f.bhi[ntp], addr);
            ldsm_x4(f.blo[ntp], addr + TILEB);
        }
    };

    auto mma_all = [&](const Frag& f) {
        #pragma unroll
        for (int mt = 0; mt < 4; ++mt)
            #pragma unroll
            for (int ntp = 0; ntp < 2; ++ntp)
                #pragma unroll
                for (int h = 0; h < 2; ++h) {
                    const uint32_t* bh = &f.bhi[ntp][h * 2];
                    const uint32_t* bl = &f.blo[ntp][h * 2];
                    float* d = acc[mt][ntp * 2 + h];
                    mma_bf16(d, f.ahi[mt], bh);
                    mma_bf16(d, f.ahi[mt], bl);
                    mma_bf16(d, f.alo[mt], bh);
                }
    };

    // prologue: stages 0 and 1 in flight
    load_stage(0, 0);
    asm volatile("cp.async.commit_group;\n" ::: "memory");
    load_stage(1, 1);
    asm volatile("cp.async.commit_group;\n" ::: "memory");
    asm volatile("cp.async.wait_group 1;\n" ::: "memory");
    __syncthreads();

    Frag fa, fb;
    load_frags(fa, sbase, 0);        // stage 0, k16-step 0

    for (int s = 0; s < KITERS; ++s) {
        const uint32_t sb_cur = sbase + (uint32_t)(s % NSTG) * STAGEB;
        if (s + 2 < KITERS) {
            load_stage(s + 2, (s + 2) % NSTG);
            asm volatile("cp.async.commit_group;\n" ::: "memory");
        }
        // prefetch step 1 of current stage, then run step 0's MMAs
        load_frags(fb, sb_cur, 1);
        mma_all(fa);

        if (s + 1 < KITERS) {
            if (s + 2 < KITERS)
                asm volatile("cp.async.wait_group 1;\n" ::: "memory");
            else
                asm volatile("cp.async.wait_group 0;\n" ::: "memory");
            __syncthreads();
            // prefetch step 0 of next stage under step 1's MMAs
            load_frags(fa, sbase + (uint32_t)((s + 1) % NSTG) * STAGEB, 0);
        }
        mma_all(fb);
    }

    // ---- epilogue: add bias, write force ----
    #pragma unroll
    for (int nt = 0; nt < 4; ++nt) {
        int c = n0 + wn + nt * 8 + (lane & 3) * 2;
        float b0 = __ldg(&bias[c]);
        float b1 = __ldg(&bias[c + 1]);
        #pragma unroll
        for (int mt = 0; mt < 4; ++mt) {
            int r = m0 + wm + mt * 16 + (lane >> 2);
            float2 lo = make_float2(acc[mt][nt][0] + b0, acc[mt][nt][1] + b1);
            float2 hi = make_float2(acc[mt][nt][2] + b0, acc[mt][nt][3] + b1);
            *reinterpret_cast<float2*>(&g_force[(size_t)r * NSZ + c]) = lo;
            *reinterpret_cast<float2*>(&g_force[(size_t)(r + 8) * NSZ + c]) = hi;
        }
    }
}

// ---------------- scan phase A: per-chunk carries (zero init) -------------
__global__ __launch_bounds__(256) void scanA_kernel(const float* __restrict__ freq,
                                                    const float* __restrict__ damp) {
    int c4 = blockIdx.x * 256 + threadIdx.x;
    int j = blockIdx.y;
    int n = c4 * 4;
    float4 f4 = *reinterpret_cast<const float4*>(freq + n);
    float4 d4 = *reinterpret_cast<const float4*>(damp + n);
    float wx = (TWO_PI * f4.x) * (TWO_PI * f4.x);
    float wy = (TWO_PI * f4.y) * (TWO_PI * f4.y);
    float wz = (TWO_PI * f4.z) * (TWO_PI * f4.z);
    float ww = (TWO_PI * f4.w) * (TWO_PI * f4.w);
    float sx = 0, sy = 0, sz = 0, sw = 0, vx = 0, vy = 0, vz = 0, vw = 0;
    const float4* fp = reinterpret_cast<const float4*>(g_force + (size_t)j * LCH * NSZ + n);
    #pragma unroll 8
    for (int k = 0; k < LCH; ++k) {
        float4 fr = fp[(size_t)k * (NSZ / 4)];
        float ax = fmaf(-wx, sx, fmaf(-d4.x, vx, fr.x)); vx = fmaf(ax, DT, vx); sx = fmaf(vx, DT, sx);
        float ay = fmaf(-wy, sy, fmaf(-d4.y, vy, fr.y)); vy = fmaf(ay, DT, vy); sy = fmaf(vy, DT, sy);
        float az = fmaf(-wz, sz, fmaf(-d4.z, vz, fr.z)); vz = fmaf(az, DT, vz); sz = fmaf(vz, DT, sz);
        float aw = fmaf(-ww, sw, fmaf(-d4.w, vw, fr.w)); vw = fmaf(aw, DT, vw); sw = fmaf(vw, DT, sw);
    }
    *reinterpret_cast<float4*>(g_cs + (size_t)j * NSZ + n) = make_float4(sx, sy, sz, sw);
    *reinterpret_cast<float4*>(g_cv + (size_t)j * NSZ + n) = make_float4(vx, vy, vz, vw);
}

// ---------------- combine: z_{j+1} = M^L z_j + carry_j --------------------
__global__ __launch_bounds__(256) void combine_kernel(const float* __restrict__ freq,
                                                      const float* __restrict__ damp) {
    int n = blockIdx.x * 256 + threadIdx.x;
    float f = freq[n], dmp = damp[n];
    float w2 = (TWO_PI * f) * (TWO_PI * f);
    float b00 = 1.0f - w2 * DT * DT;
    float b01 = DT * (1.0f - dmp * DT);
    float b10 = -w2 * DT;
    float b11 = 1.0f - dmp * DT;
    float e00 = 1.0f, e01 = 0.0f, e10 = 0.0f, e11 = 1.0f;
    int p = LCH;
    while (p) {
        if (p & 1) {
            float t00 = b00 * e00 + b01 * e10, t01 = b00 * e01 + b01 * e11;
            float t10 = b10 * e00 + b11 * e10, t11 = b10 * e01 + b11 * e11;
            e00 = t00; e01 = t01; e10 = t10; e11 = t11;
        }
        float s00 = b00 * b00 + b01 * b10, s01 = b00 * b01 + b01 * b11;
        float s10 = b10 * b00 + b11 * b10, s11 = b10 * b01 + b11 * b11;
        b00 = s00; b01 = s01; b10 = s10; b11 = s11;
        p >>= 1;
    }
    float sz = 0.0f, vz = 0.0f;
    for (int j = 0; j < CCH; ++j) {
        g_zs[j * NSZ + n] = sz;
        g_zv[j * NSZ + n] = vz;
        float cs = g_cs[j * NSZ + n], cv = g_cv[j * NSZ + n];
        float ns = e00 * sz + e01 * vz + cs;
        float nv = e10 * sz + e11 * vz + cv;
        sz = ns; vz = nv;
    }
}

// ---------------- scan phase B: full scan from z, + osc, clip, write ------
__global__ __launch_bounds__(256) void scanB_kernel(const float* __restrict__ freq,
                                                    const float* __restrict__ damp,
                                                    const float* __restrict__ amp,
                                                    const float* __restrict__ phase,
                                                    float* __restrict__ out) {
    int c4 = blockIdx.x * 256 + threadIdx.x;
    int j = blockIdx.y;
    int n = c4 * 4;
    float4 f4 = *reinterpret_cast<const float4*>(freq + n);
    float4 d4 = *reinterpret_cast<const float4*>(damp + n);
    float4 a4 = *reinterpret_cast<const float4*>(amp + n);
    float4 p4 = *reinterpret_cast<const float4*>(phase + n);
    float wx = (TWO_PI * f4.x) * (TWO_PI * f4.x);
    float wy = (TWO_PI * f4.y) * (TWO_PI * f4.y);
    float wz = (TWO_PI * f4.z) * (TWO_PI * f4.z);
    float ww = (TWO_PI * f4.w) * (TWO_PI * f4.w);
    float ox = a4.x * sinf(fmaf(TWO_PI * f4.x, DT, p4.x));
    float oy = a4.y * sinf(fmaf(TWO_PI * f4.y, DT, p4.y));
    float oz = a4.z * sinf(fmaf(TWO_PI * f4.z, DT, p4.z));
    float ow = a4.w * sinf(fmaf(TWO_PI * f4.w, DT, p4.w));
    float4 zs = *reinterpret_cast<const float4*>(g_zs + (size_t)j * NSZ + n);
    float4 zv = *reinterpret_cast<const float4*>(g_zv + (size_t)j * NSZ + n);
    float sx = zs.x, sy = zs.y, szz = zs.z, sww = zs.w;
    float vx = zv.x, vy = zv.y, vzz = zv.z, vww = zv.w;
    const float4* fp = reinterpret_cast<const float4*>(g_force + (size_t)j * LCH * NSZ + n);
    float4* op = reinterpret_cast<float4*>(out + (size_t)j * LCH * NSZ + n);
    #pragma unroll 8
    for (int k = 0; k < LCH; ++k) {
        float4 fr = fp[(size_t)k * (NSZ / 4)];
        float ax = fmaf(-wx, sx, fmaf(-d4.x, vx, fr.x)); vx = fmaf(ax, DT, vx); sx = fmaf(vx, DT, sx);
        float ay = fmaf(-wy, sy, fmaf(-d4.y, vy, fr.y)); vy = fmaf(ay, DT, vy); sy = fmaf(vy, DT, sy);
        float az = fmaf(-wz, szz, fmaf(-d4.z, vzz, fr.z)); vzz = fmaf(az, DT, vzz); szz = fmaf(vzz, DT, szz);
        float aw = fmaf(-ww, sww, fmaf(-d4.w, vww, fr.w)); vww = fmaf(aw, DT, vww); sww = fmaf(vww, DT, sww);
        float4 o;
        o.x = fminf(1.0f, fmaxf(-1.0f, sx + ox));
        o.y = fminf(1.0f, fmaxf(-1.0f, sy + oy));
        o.z = fminf(1.0f, fmaxf(-1.0f, szz + oz));
        o.w = fminf(1.0f, fmaxf(-1.0f, sww + ow));
        op[(size_t)k * (NSZ / 4)] = o;
    }
}

// ---------------------------------------------------------------------------
extern "C" void kernel_launch(void* const* d_in, const int* in_sizes, int n_in,
                              void* d_out, int out_size)
{
    const float* x     = (const float*)d_in[0];
    const float* W     = (const float*)d_in[1];
    const float* b     = (const float*)d_in[2];
    const float* amp   = (const float*)d_in[3];
    const float* freq  = (const float*)d_in[4];
    const float* phase = (const float*)d_in[5];
    const float* damp  = (const float*)d_in[6];
    float* out = (float*)d_out;
    (void)in_sizes; (void)n_in; (void)out_size;

    static bool attr_done = false;
    if (!attr_done) {
        cudaFuncSetAttribute(gemm_bf16x3_kernel,
                             cudaFuncAttributeMaxDynamicSharedMemorySize, SMEM_BYTES);
        attr_done = true;
    }

    // 1. split operands into bf16 hi + bf16 residual lo
    splitA_kernel<<<(BSZ * DSZ / 4) / 256, 256>>>(x);
    splitW_kernel<<<(NSZ * DSZ / 4) / 256, 256>>>(W);

    // 2. bf16x3 tensor-core GEMM -> g_force (bias fused in epilogue)
    dim3 ggrid(NSZ / GBN, BSZ / GBM);
    gemm_bf16x3_kernel<<<ggrid, 256, SMEM_BYTES>>>(b);

    // 3. chunked parallel scan
    dim3 sgrid(NSZ / 4 / 256, CCH);
    scanA_kernel<<<sgrid, 256>>>(freq, damp);
    combine_kernel<<<NSZ / 256, 256>>>(freq, damp);
    scanB_kernel<<<sgrid, 256>>>(freq, damp, amp, phase, out);
}